// round 12
// baseline (speedup 1.0000x reference)
#include <cuda_runtime.h>
#include <cuda_bf16.h>

// RUDY congestion map — 2 launches.
//
// Kernel 1 (scatter): 4 lanes/net, quad-shfl bbox, <=2 red.global.add.v4.f32
//   per x-breakpoint into parity-split diff arrays:
//     E: {H,V} at (px*DPITCH+y)*2  (even-start y-pairs)
//     O: {H,V} at px*1024+(y-1)*2  (odd-start y-pairs; E shifted one y)
// Kernel 2 (fused scans, 128 blocks = single wave, one CTA/SM):
//   row phase: inclusive y-scan of E[y]+O[y-1] per x-row (4 rows/block),
//              zero-restores O.
//   [tight-spin software grid barrier — 128 co-resident CTAs]
//   col phase: ALL 128 blocks x-scan 4 y-columns, out = max(|h|,|v|),
//              zero-restores E.  Arrays pristine for the next graph replay.

#define NBX 512
#define NBY 512
#define DPITCH 516
#define DROWS  513
#define SBLK 128            // scan kernel blocks (single wave, all resident)
#define NTHR 512

__device__ float g_diffE[DROWS * DPITCH * 2];   // zero-init
__device__ float g_diffO[NBX * 1024];           // zero-init
__device__ unsigned g_barcnt;                   // 0 at rest
__device__ unsigned g_bargen;                   // grows monotonically (ok)

__device__ __forceinline__ float edge(int i, float bs) {
    return (float)i * bs;   // bs = 1000/512 exact; i*bs exact in range
}

__device__ __forceinline__ float fval(float vmin, float vmax, int i, float bs) {
    float ov = fminf(vmax, edge(i + 1, bs)) - fmaxf(vmin, edge(i, bs));
    return fminf(fmaxf(ov, 0.0f), bs);
}

__device__ __forceinline__ int bin_of(float v, float inv_bs, float bs, int nb) {
    int i = (int)(v * inv_bs);
    if (i > nb - 1) i = nb - 1;
    if (i < 0) i = 0;
    if (i > 0 && v < edge(i, bs)) --i;
    else if (i < nb - 1 && v >= edge(i + 1, bs)) ++i;
    return i;
}

__device__ __forceinline__ void red_add_v4(float* p, float a, float b,
                                           float c, float d) {
    asm volatile("red.global.add.v4.f32 [%0], {%1, %2, %3, %4};"
                 :: "l"(p), "f"(a), "f"(b), "f"(c), "f"(d) : "memory");
}

__global__ void scatter_kernel(const float* __restrict__ pin_pos,
                               const float* __restrict__ net_weights,
                               const int* __restrict__ netpin_start,
                               const int* __restrict__ flat_netpin,
                               int num_nets, int P) {
    const float BSX = 1.953125f;          // 1000/512, exact
    const float BSY = 1.953125f;
    const float INV_BSX = 1.0f / 1.953125f;
    const float INV_BSY = 1.0f / 1.953125f;
    const float SCALE = 262144.0f / 100000.0f;  // 1/(BSX*BSY*0.1)

    int gt = blockIdx.x * blockDim.x + threadIdx.x;
    int n = gt >> 2;          // one net per quad of lanes
    int sub = gt & 3;
    bool valid = (n < num_nets);

    float xmin = 3.0e38f, xmax = -3.0e38f, ymin = 3.0e38f, ymax = -3.0e38f;
    int s = 0, cnt = 0;
    if (valid) {
        s = netpin_start[n];
        cnt = netpin_start[n + 1] - s;
    }

    // lane sub gathers pins sub, sub+4 (covers cnt<=8), fallback for more
    if (sub < cnt) {
        int id = __ldg(&flat_netpin[s + sub]);
        float x = __ldg(&pin_pos[id]);
        float y = __ldg(&pin_pos[P + id]);
        xmin = fminf(xmin, x); xmax = fmaxf(xmax, x);
        ymin = fminf(ymin, y); ymax = fmaxf(ymax, y);
    }
    if (sub + 4 < cnt) {
        int id = __ldg(&flat_netpin[s + sub + 4]);
        float x = __ldg(&pin_pos[id]);
        float y = __ldg(&pin_pos[P + id]);
        xmin = fminf(xmin, x); xmax = fmaxf(xmax, x);
        ymin = fminf(ymin, y); ymax = fmaxf(ymax, y);
    }
    for (int k = sub + 8; k < cnt; k += 4) {
        int id = __ldg(&flat_netpin[s + k]);
        float x = __ldg(&pin_pos[id]);
        float y = __ldg(&pin_pos[P + id]);
        xmin = fminf(xmin, x); xmax = fmaxf(xmax, x);
        ymin = fminf(ymin, y); ymax = fmaxf(ymax, y);
    }

    // quad butterfly: combine bbox across 4 lanes (xor 1, then 2).
    // Whole warp executes (no early return above); quads never mix.
#pragma unroll
    for (int o = 1; o <= 2; o <<= 1) {
        xmin = fminf(xmin, __shfl_xor_sync(0xffffffff, xmin, o));
        xmax = fmaxf(xmax, __shfl_xor_sync(0xffffffff, xmax, o));
        ymin = fminf(ymin, __shfl_xor_sync(0xffffffff, ymin, o));
        ymax = fmaxf(ymax, __shfl_xor_sync(0xffffffff, ymax, o));
    }

    if (!valid) return;

    float sx = xmax - xmin;
    float sy = ymax - ymin;
    // zero span in either dim zeroes the ox*oy product for BOTH maps
    if (!(sx > 0.0f) || !(sy > 0.0f)) return;

    float wt = __ldg(&net_weights[n]) * SCALE;
    float wh = wt / sy;   // horizontal demand weight
    float wv = wt / sx;   // vertical demand weight

    int lox = bin_of(xmin, INV_BSX, BSX, NBX);
    int hix = bin_of(xmax, INV_BSX, BSX, NBX);
    int loy = bin_of(ymin, INV_BSY, BSY, NBY);
    int hiy = bin_of(ymax, INV_BSY, BSY, NBY);

    // lane sub owns x-breakpoint sub: {lox, lox+1, hix, hix+1} with dedup.
    int px = (sub < 2) ? (lox + sub) : (hix + (sub - 2));
    bool xok = (sub < 2) || (sub == 2 ? (hix > lox + 1) : (hix > lox));
    if (!xok || px >= NBX) return;     // index-512 positions are dead

    float dx = fval(xmin, xmax, px, BSX) - fval(xmin, xmax, px - 1, BSX);
    float ah = wh * dx;
    float av = wv * dx;

    // lo pair (loy, loy+1): both positions always in the support
    {
        float f0 = fval(ymin, ymax, loy, BSY);
        float d0 = f0;                                      // fval(loy-1)=0
        float d1 = fval(ymin, ymax, loy + 1, BSY) - f0;
        float* p = (loy & 1)
            ? &g_diffO[px * 1024 + (loy - 1) * 2]
            : &g_diffE[(px * DPITCH + loy) * 2];
        red_add_v4(p, ah * d0, av * d0, ah * d1, av * d1);
    }
    // hi pair (hiy, hiy+1): hiy only if hiy>loy+1, hiy+1 only if hiy>loy.
    // (position 512 lands in a dead slot of O, restored by the scan kernel.)
    if (hiy > loy) {
        float fh = fval(ymin, ymax, hiy, BSY);
        float e0 = (hiy > loy + 1)
                 ? (fh - fval(ymin, ymax, hiy - 1, BSY)) : 0.0f;
        float e1 = fval(ymin, ymax, hiy + 1, BSY) - fh;
        float* p = (hiy & 1)
            ? &g_diffO[px * 1024 + (hiy - 1) * 2]
            : &g_diffE[(px * DPITCH + hiy) * 2];
        red_add_v4(p, ah * e0, av * e0, ah * e1, av * e1);
    }
}

// tight-spin grid barrier for exactly SBLK co-resident CTAs.
__device__ __forceinline__ void grid_barrier() {
    __threadfence();
    __syncthreads();
    if (threadIdx.x == 0) {
        volatile unsigned* vgen = (volatile unsigned*)&g_bargen;
        volatile unsigned* vcnt = (volatile unsigned*)&g_barcnt;
        unsigned gen = *vgen;
        if (atomicAdd(&g_barcnt, 1u) == SBLK - 1) {
            *vcnt = 0;
            __threadfence();
            atomicAdd(&g_bargen, 1u);          // release
        } else {
            while (*vgen == gen) { }           // tight spin (L2 poll)
        }
    }
    __syncthreads();
    __threadfence();
}

// fused scans: row phase (y-scan, 4 rows/block, restores O), grid barrier,
// col phase (x-scan + finalize on ALL blocks, restores E).
__global__ void __launch_bounds__(NTHR, 2)
scan_finalize_kernel(float* __restrict__ out) {
    __shared__ float ws[8][16];
    int tid = threadIdx.x;
    int bid = blockIdx.x;
    int lane = tid & 31, wid = tid >> 5;

    // ---------- row phase: rows bid, bid+128, bid+256, bid+384 ----------
#pragma unroll
    for (int r = 0; r < NBX / SBLK; ++r) {
        int row = bid + r * SBLK;
        float2* E = reinterpret_cast<float2*>(g_diffE) + row * DPITCH;
        float2* O = reinterpret_cast<float2*>(g_diffO) + row * 512;

        float2 hv = E[tid];
        float h = hv.x, v = hv.y;
        if (tid >= 1) {
            float2 o = O[tid - 1];
            h += o.x; v += o.y;
            O[tid - 1] = make_float2(0.f, 0.f);    // restore zeros
        } else {
            O[511] = make_float2(0.f, 0.f);        // dead y=512 slot
        }

#pragma unroll
        for (int o = 1; o < 32; o <<= 1) {
            float nh = __shfl_up_sync(0xffffffff, h, o);
            float nv = __shfl_up_sync(0xffffffff, v, o);
            if (lane >= o) { h += nh; v += nv; }
        }
        if (lane == 31) { ws[0][wid] = h; ws[1][wid] = v; }
        __syncthreads();
        if (wid == 0) {
            float sv = (lane < 16) ? ws[0][lane] : ws[1][lane - 16];
#pragma unroll
            for (int o = 1; o < 16; o <<= 1) {
                float nv = __shfl_up_sync(0xffffffff, sv, o, 16);
                if ((lane & 15) >= o) sv += nv;
            }
            if (lane < 16) ws[0][lane] = sv; else ws[1][lane - 16] = sv;
        }
        __syncthreads();
        if (wid > 0) { h += ws[0][wid - 1]; v += ws[1][wid - 1]; }
        E[tid] = make_float2(h, v);
        __syncthreads();               // ws reuse safety
    }

    grid_barrier();

    // ---------- col phase: 4 y-columns per block, all 128 blocks ----------
    {
        int y0 = bid * 4;

        float* base = &g_diffE[(tid * DPITCH + y0) * 2];   // 16B aligned
        float4 qa = *reinterpret_cast<const float4*>(base);
        float4 qb = *reinterpret_cast<const float4*>(base + 4);
        float s0 = qa.x, s1 = qa.y, s2 = qa.z, s3 = qa.w;
        float s4 = qb.x, s5 = qb.y, s6 = qb.z, s7 = qb.w;

#pragma unroll
        for (int o = 1; o < 32; o <<= 1) {
            float n0 = __shfl_up_sync(0xffffffff, s0, o);
            float n1 = __shfl_up_sync(0xffffffff, s1, o);
            float n2 = __shfl_up_sync(0xffffffff, s2, o);
            float n3 = __shfl_up_sync(0xffffffff, s3, o);
            float n4 = __shfl_up_sync(0xffffffff, s4, o);
            float n5 = __shfl_up_sync(0xffffffff, s5, o);
            float n6 = __shfl_up_sync(0xffffffff, s6, o);
            float n7 = __shfl_up_sync(0xffffffff, s7, o);
            if (lane >= o) {
                s0 += n0; s1 += n1; s2 += n2; s3 += n3;
                s4 += n4; s5 += n5; s6 += n6; s7 += n7;
            }
        }
        if (lane == 31) {
            ws[0][wid] = s0; ws[1][wid] = s1; ws[2][wid] = s2; ws[3][wid] = s3;
            ws[4][wid] = s4; ws[5][wid] = s5; ws[6][wid] = s6; ws[7][wid] = s7;
        }
        __syncthreads();
        if (wid < 8 && lane < 16) {
            float sv = ws[wid][lane];
#pragma unroll
            for (int o = 1; o < 16; o <<= 1) {
                float nv = __shfl_up_sync(0x0000ffff, sv, o, 16);
                if (lane >= o) sv += nv;
            }
            ws[wid][lane] = sv;
        }
        __syncthreads();
        if (wid > 0) {
            s0 += ws[0][wid - 1]; s1 += ws[1][wid - 1];
            s2 += ws[2][wid - 1]; s3 += ws[3][wid - 1];
            s4 += ws[4][wid - 1]; s5 += ws[5][wid - 1];
            s6 += ws[6][wid - 1]; s7 += ws[7][wid - 1];
        }

        // restore zeros for the next replay
        float4 z = make_float4(0.f, 0.f, 0.f, 0.f);
        *reinterpret_cast<float4*>(base) = z;
        *reinterpret_cast<float4*>(base + 4) = z;

        *reinterpret_cast<float4*>(&out[tid * NBY + y0]) =
            make_float4(fmaxf(fabsf(s0), fabsf(s1)),
                        fmaxf(fabsf(s2), fabsf(s3)),
                        fmaxf(fabsf(s4), fabsf(s5)),
                        fmaxf(fabsf(s6), fabsf(s7)));
    }
}

extern "C" void kernel_launch(void* const* d_in, const int* in_sizes, int n_in,
                              void* d_out, int out_size) {
    const float* pin_pos      = (const float*)d_in[0];
    const float* net_weights  = (const float*)d_in[1];
    const int*   netpin_start = (const int*)d_in[2];
    const int*   flat_netpin  = (const int*)d_in[3];
    float* out = (float*)d_out;

    int P = in_sizes[0] / 2;
    int num_nets = in_sizes[2] - 1;

    int threads = num_nets * 4;
    scatter_kernel<<<(threads + 255) / 256, 256>>>(
        pin_pos, net_weights, netpin_start, flat_netpin, num_nets, P);
    scan_finalize_kernel<<<SBLK, NTHR>>>(out);
}

// round 13
// speedup vs baseline: 1.0909x; 1.0909x over previous
#include <cuda_runtime.h>
#include <cuda_bf16.h>

// RUDY congestion map — 2 launches.
//
// Kernel 1 (scatter): 4 lanes/net, quad-shfl bbox, <=2 red.global.add.v4.f32
//   per x-breakpoint into parity-split diff arrays:
//     E: {H,V} at (px*DPITCH+y)*2  (even-start y-pairs)
//     O: {H,V} at px*1024+(y-1)*2  (odd-start y-pairs; E shifted one y)
// Kernel 2 (fused scans, 128 blocks = single wave, one CTA/SM):
//   row phase: ONE pass, 4 rows per block scanned simultaneously (8-value
//              shuffle scan, full ILP), zero-restores O.
//   [tight-spin software grid barrier — 128 co-resident CTAs]
//   col phase: 4 y-columns per block, out = max(|h|,|v|), zero-restores E.
//   Arrays pristine at exit for the next graph replay.

#define NBX 512
#define NBY 512
#define DPITCH 516
#define DROWS  513
#define SBLK 128            // scan kernel blocks (single wave, all resident)
#define NTHR 512

__device__ float g_diffE[DROWS * DPITCH * 2];   // zero-init
__device__ float g_diffO[NBX * 1024];           // zero-init
__device__ unsigned g_barcnt;                   // 0 at rest
__device__ unsigned g_bargen;                   // grows monotonically (ok)

__device__ __forceinline__ float edge(int i, float bs) {
    return (float)i * bs;   // bs = 1000/512 exact; i*bs exact in range
}

__device__ __forceinline__ float fval(float vmin, float vmax, int i, float bs) {
    float ov = fminf(vmax, edge(i + 1, bs)) - fmaxf(vmin, edge(i, bs));
    return fminf(fmaxf(ov, 0.0f), bs);
}

__device__ __forceinline__ int bin_of(float v, float inv_bs, float bs, int nb) {
    int i = (int)(v * inv_bs);
    if (i > nb - 1) i = nb - 1;
    if (i < 0) i = 0;
    if (i > 0 && v < edge(i, bs)) --i;
    else if (i < nb - 1 && v >= edge(i + 1, bs)) ++i;
    return i;
}

__device__ __forceinline__ void red_add_v4(float* p, float a, float b,
                                           float c, float d) {
    asm volatile("red.global.add.v4.f32 [%0], {%1, %2, %3, %4};"
                 :: "l"(p), "f"(a), "f"(b), "f"(c), "f"(d) : "memory");
}

__global__ void scatter_kernel(const float* __restrict__ pin_pos,
                               const float* __restrict__ net_weights,
                               const int* __restrict__ netpin_start,
                               const int* __restrict__ flat_netpin,
                               int num_nets, int P) {
    const float BSX = 1.953125f;          // 1000/512, exact
    const float BSY = 1.953125f;
    const float INV_BSX = 1.0f / 1.953125f;
    const float INV_BSY = 1.0f / 1.953125f;
    const float SCALE = 262144.0f / 100000.0f;  // 1/(BSX*BSY*0.1)

    int gt = blockIdx.x * blockDim.x + threadIdx.x;
    int n = gt >> 2;          // one net per quad of lanes
    int sub = gt & 3;
    bool valid = (n < num_nets);

    float xmin = 3.0e38f, xmax = -3.0e38f, ymin = 3.0e38f, ymax = -3.0e38f;
    int s = 0, cnt = 0;
    if (valid) {
        s = netpin_start[n];
        cnt = netpin_start[n + 1] - s;
    }

    // lane sub gathers pins sub, sub+4 (covers cnt<=8), fallback for more
    if (sub < cnt) {
        int id = __ldg(&flat_netpin[s + sub]);
        float x = __ldg(&pin_pos[id]);
        float y = __ldg(&pin_pos[P + id]);
        xmin = fminf(xmin, x); xmax = fmaxf(xmax, x);
        ymin = fminf(ymin, y); ymax = fmaxf(ymax, y);
    }
    if (sub + 4 < cnt) {
        int id = __ldg(&flat_netpin[s + sub + 4]);
        float x = __ldg(&pin_pos[id]);
        float y = __ldg(&pin_pos[P + id]);
        xmin = fminf(xmin, x); xmax = fmaxf(xmax, x);
        ymin = fminf(ymin, y); ymax = fmaxf(ymax, y);
    }
    for (int k = sub + 8; k < cnt; k += 4) {
        int id = __ldg(&flat_netpin[s + k]);
        float x = __ldg(&pin_pos[id]);
        float y = __ldg(&pin_pos[P + id]);
        xmin = fminf(xmin, x); xmax = fmaxf(xmax, x);
        ymin = fminf(ymin, y); ymax = fmaxf(ymax, y);
    }

    // quad butterfly: combine bbox across 4 lanes (xor 1, then 2).
    // Whole warp executes (no early return above); quads never mix.
#pragma unroll
    for (int o = 1; o <= 2; o <<= 1) {
        xmin = fminf(xmin, __shfl_xor_sync(0xffffffff, xmin, o));
        xmax = fmaxf(xmax, __shfl_xor_sync(0xffffffff, xmax, o));
        ymin = fminf(ymin, __shfl_xor_sync(0xffffffff, ymin, o));
        ymax = fmaxf(ymax, __shfl_xor_sync(0xffffffff, ymax, o));
    }

    if (!valid) return;

    float sx = xmax - xmin;
    float sy = ymax - ymin;
    // zero span in either dim zeroes the ox*oy product for BOTH maps
    if (!(sx > 0.0f) || !(sy > 0.0f)) return;

    float wt = __ldg(&net_weights[n]) * SCALE;
    float wh = wt / sy;   // horizontal demand weight
    float wv = wt / sx;   // vertical demand weight

    int lox = bin_of(xmin, INV_BSX, BSX, NBX);
    int hix = bin_of(xmax, INV_BSX, BSX, NBX);
    int loy = bin_of(ymin, INV_BSY, BSY, NBY);
    int hiy = bin_of(ymax, INV_BSY, BSY, NBY);

    // lane sub owns x-breakpoint sub: {lox, lox+1, hix, hix+1} with dedup.
    int px = (sub < 2) ? (lox + sub) : (hix + (sub - 2));
    bool xok = (sub < 2) || (sub == 2 ? (hix > lox + 1) : (hix > lox));
    if (!xok || px >= NBX) return;     // index-512 positions are dead

    float dx = fval(xmin, xmax, px, BSX) - fval(xmin, xmax, px - 1, BSX);
    float ah = wh * dx;
    float av = wv * dx;

    // lo pair (loy, loy+1): both positions always in the support
    {
        float f0 = fval(ymin, ymax, loy, BSY);
        float d0 = f0;                                      // fval(loy-1)=0
        float d1 = fval(ymin, ymax, loy + 1, BSY) - f0;
        float* p = (loy & 1)
            ? &g_diffO[px * 1024 + (loy - 1) * 2]
            : &g_diffE[(px * DPITCH + loy) * 2];
        red_add_v4(p, ah * d0, av * d0, ah * d1, av * d1);
    }
    // hi pair (hiy, hiy+1): hiy only if hiy>loy+1, hiy+1 only if hiy>loy.
    // (position 512 lands in a dead slot of O, restored by the scan kernel.)
    if (hiy > loy) {
        float fh = fval(ymin, ymax, hiy, BSY);
        float e0 = (hiy > loy + 1)
                 ? (fh - fval(ymin, ymax, hiy - 1, BSY)) : 0.0f;
        float e1 = fval(ymin, ymax, hiy + 1, BSY) - fh;
        float* p = (hiy & 1)
            ? &g_diffO[px * 1024 + (hiy - 1) * 2]
            : &g_diffE[(px * DPITCH + hiy) * 2];
        red_add_v4(p, ah * e0, av * e0, ah * e1, av * e1);
    }
}

// tight-spin grid barrier for exactly SBLK co-resident CTAs.
__device__ __forceinline__ void grid_barrier() {
    __threadfence();
    __syncthreads();
    if (threadIdx.x == 0) {
        volatile unsigned* vgen = (volatile unsigned*)&g_bargen;
        volatile unsigned* vcnt = (volatile unsigned*)&g_barcnt;
        unsigned gen = *vgen;
        if (atomicAdd(&g_barcnt, 1u) == SBLK - 1) {
            *vcnt = 0;
            __threadfence();
            atomicAdd(&g_bargen, 1u);          // release
        } else {
            while (*vgen == gen) { }           // tight spin (L2 poll)
        }
    }
    __syncthreads();
    __threadfence();
}

// 8-value inclusive block scan over the 512-thread dimension; values are
// (pairs of) independent sequences.  ws must be __shared__ float[8][16].
#define BLOCK_SCAN8(s0,s1,s2,s3,s4,s5,s6,s7, ws, lane, wid)                    \
    do {                                                                       \
        _Pragma("unroll")                                                      \
        for (int o = 1; o < 32; o <<= 1) {                                     \
            float n0 = __shfl_up_sync(0xffffffff, s0, o);                      \
            float n1 = __shfl_up_sync(0xffffffff, s1, o);                      \
            float n2 = __shfl_up_sync(0xffffffff, s2, o);                      \
            float n3 = __shfl_up_sync(0xffffffff, s3, o);                      \
            float n4 = __shfl_up_sync(0xffffffff, s4, o);                      \
            float n5 = __shfl_up_sync(0xffffffff, s5, o);                      \
            float n6 = __shfl_up_sync(0xffffffff, s6, o);                      \
            float n7 = __shfl_up_sync(0xffffffff, s7, o);                      \
            if (lane >= o) {                                                   \
                s0 += n0; s1 += n1; s2 += n2; s3 += n3;                        \
                s4 += n4; s5 += n5; s6 += n6; s7 += n7;                        \
            }                                                                  \
        }                                                                      \
        if (lane == 31) {                                                      \
            ws[0][wid] = s0; ws[1][wid] = s1; ws[2][wid] = s2; ws[3][wid] = s3;\
            ws[4][wid] = s4; ws[5][wid] = s5; ws[6][wid] = s6; ws[7][wid] = s7;\
        }                                                                      \
        __syncthreads();                                                       \
        if (wid < 8 && lane < 16) {                                            \
            float sv = ws[wid][lane];                                          \
            _Pragma("unroll")                                                  \
            for (int o = 1; o < 16; o <<= 1) {                                 \
                float nv = __shfl_up_sync(0x0000ffff, sv, o, 16);              \
                if (lane >= o) sv += nv;                                       \
            }                                                                  \
            ws[wid][lane] = sv;                                                \
        }                                                                      \
        __syncthreads();                                                       \
        if (wid > 0) {                                                         \
            s0 += ws[0][wid - 1]; s1 += ws[1][wid - 1];                        \
            s2 += ws[2][wid - 1]; s3 += ws[3][wid - 1];                        \
            s4 += ws[4][wid - 1]; s5 += ws[5][wid - 1];                        \
            s6 += ws[6][wid - 1]; s7 += ws[7][wid - 1];                        \
        }                                                                      \
    } while (0)

// fused scans: row phase (4 rows at once, 8-wide ILP, restores O),
// grid barrier, col phase (4 y-columns, restores E).
__global__ void __launch_bounds__(NTHR, 2)
scan_finalize_kernel(float* __restrict__ out) {
    __shared__ float ws[8][16];
    int tid = threadIdx.x;
    int bid = blockIdx.x;
    int lane = tid & 31, wid = tid >> 5;

    // ---------- row phase: rows bid, bid+128, bid+256, bid+384, one pass ----
    {
        int r0 = bid, r1 = bid + SBLK, r2 = bid + 2 * SBLK, r3 = bid + 3 * SBLK;
        float2* E0 = reinterpret_cast<float2*>(g_diffE) + r0 * DPITCH;
        float2* E1 = reinterpret_cast<float2*>(g_diffE) + r1 * DPITCH;
        float2* E2 = reinterpret_cast<float2*>(g_diffE) + r2 * DPITCH;
        float2* E3 = reinterpret_cast<float2*>(g_diffE) + r3 * DPITCH;
        float2* O0 = reinterpret_cast<float2*>(g_diffO) + r0 * 512;
        float2* O1 = reinterpret_cast<float2*>(g_diffO) + r1 * 512;
        float2* O2 = reinterpret_cast<float2*>(g_diffO) + r2 * 512;
        float2* O3 = reinterpret_cast<float2*>(g_diffO) + r3 * 512;

        // all 8 loads issued independently (+4 O loads) — deep MLP
        float2 e0 = E0[tid], e1 = E1[tid], e2 = E2[tid], e3 = E3[tid];
        float2 zz = make_float2(0.f, 0.f);
        if (tid >= 1) {
            float2 o0 = O0[tid - 1], o1 = O1[tid - 1];
            float2 o2 = O2[tid - 1], o3 = O3[tid - 1];
            e0.x += o0.x; e0.y += o0.y;  e1.x += o1.x; e1.y += o1.y;
            e2.x += o2.x; e2.y += o2.y;  e3.x += o3.x; e3.y += o3.y;
            O0[tid - 1] = zz; O1[tid - 1] = zz;
            O2[tid - 1] = zz; O3[tid - 1] = zz;
        } else {
            O0[511] = zz; O1[511] = zz; O2[511] = zz; O3[511] = zz;  // dead y=512
        }

        float s0 = e0.x, s1 = e0.y, s2 = e1.x, s3 = e1.y;
        float s4 = e2.x, s5 = e2.y, s6 = e3.x, s7 = e3.y;

        BLOCK_SCAN8(s0, s1, s2, s3, s4, s5, s6, s7, ws, lane, wid);

        E0[tid] = make_float2(s0, s1);
        E1[tid] = make_float2(s2, s3);
        E2[tid] = make_float2(s4, s5);
        E3[tid] = make_float2(s6, s7);
    }

    grid_barrier();

    // ---------- col phase: 4 y-columns per block, all 128 blocks ----------
    {
        int y0 = bid * 4;

        float* base = &g_diffE[(tid * DPITCH + y0) * 2];   // 16B aligned
        float4 qa = *reinterpret_cast<const float4*>(base);
        float4 qb = *reinterpret_cast<const float4*>(base + 4);
        float s0 = qa.x, s1 = qa.y, s2 = qa.z, s3 = qa.w;
        float s4 = qb.x, s5 = qb.y, s6 = qb.z, s7 = qb.w;

        BLOCK_SCAN8(s0, s1, s2, s3, s4, s5, s6, s7, ws, lane, wid);

        // restore zeros for the next replay
        float4 z = make_float4(0.f, 0.f, 0.f, 0.f);
        *reinterpret_cast<float4*>(base) = z;
        *reinterpret_cast<float4*>(base + 4) = z;

        *reinterpret_cast<float4*>(&out[tid * NBY + y0]) =
            make_float4(fmaxf(fabsf(s0), fabsf(s1)),
                        fmaxf(fabsf(s2), fabsf(s3)),
                        fmaxf(fabsf(s4), fabsf(s5)),
                        fmaxf(fabsf(s6), fabsf(s7)));
    }
}

extern "C" void kernel_launch(void* const* d_in, const int* in_sizes, int n_in,
                              void* d_out, int out_size) {
    const float* pin_pos      = (const float*)d_in[0];
    const float* net_weights  = (const float*)d_in[1];
    const int*   netpin_start = (const int*)d_in[2];
    const int*   flat_netpin  = (const int*)d_in[3];
    float* out = (float*)d_out;

    int P = in_sizes[0] / 2;
    int num_nets = in_sizes[2] - 1;

    int threads = num_nets * 4;
    scatter_kernel<<<(threads + 255) / 256, 256>>>(
        pin_pos, net_weights, netpin_start, flat_netpin, num_nets, P);
    scan_finalize_kernel<<<SBLK, NTHR>>>(out);
}